// round 4
// baseline (speedup 1.0000x reference)
#include <cuda_runtime.h>

// ---------------------------------------------------------------------------
// GNNEncoder: 2-layer GCN. out[d] = dinv[d]*sum_{(s,d)}(x[s]@W)*dinv[s] + b
// R4: packed-f32x2 (FFMA2) smem-tiled GEMM (2x fp32 FLOP/issue, exact math),
//     4-way MLP-unrolled gather aggregation, single-block smem CSR scan.
// edge_index dtype detected at runtime (int32 vs int64-as-int32-pairs).
// All scratch in __device__ globals; graph-capturable (kernel launches only).
// ---------------------------------------------------------------------------

#define NODES_MAX 50000
#define EDGES_MAX 800000

__device__ int   g_odd_or;                 // !=0  =>  edge_index is int32
__device__ int   g_cnt[NODES_MAX];
__device__ int   g_off[NODES_MAX + 1];
__device__ int   g_cursor[NODES_MAX];
__device__ int   g_csr_src[EDGES_MAX];
__device__ float g_dinv[NODES_MAX];
__device__ float g_hs [NODES_MAX * 128];   // layer1 (x@W1)*dinv
__device__ float g_x2 [NODES_MAX * 128];   // layer1 output (post relu)
__device__ float g_hs2[NODES_MAX * 64];    // layer2 (x2@W2)*dinv

// ---- f32x2 helpers --------------------------------------------------------
__device__ __forceinline__ unsigned long long pack2(float lo, float hi)
{
    unsigned long long r;
    asm("mov.b64 %0, {%1, %2};" : "=l"(r) : "f"(lo), "f"(hi));
    return r;
}
__device__ __forceinline__ void unpack2(unsigned long long v, float& lo, float& hi)
{
    asm("mov.b64 {%0, %1}, %2;" : "=f"(lo), "=f"(hi) : "l"(v));
}
__device__ __forceinline__ void ffma2(unsigned long long& d,
                                      unsigned long long a,
                                      unsigned long long b)
{
    asm("fma.rn.f32x2 %0, %1, %2, %3;" : "=l"(d) : "l"(a), "l"(b), "l"(d));
}

// ---- CSR build --------------------------------------------------------------
__global__ void k_init(const int* __restrict__ v, int N)
{
    int i = blockIdx.x * blockDim.x + threadIdx.x;
    if (i < N) g_cnt[i] = 0;
    if (i == 0) g_odd_or = 0;
    // dtype detect: int64 viewed as int32 pairs -> odd words all zero.
    if (i < 256) {
        if (v[2 * i + 1] != 0) atomicOr(&g_odd_or, 1);
    }
}

__global__ void k_hist(const int* __restrict__ v, int E, int N)
{
    int i = blockIdx.x * blockDim.x + threadIdx.x;
    if (i >= E) return;
    int is32  = g_odd_or;
    int s     = is32 ? 1 : 2;
    int dbase = is32 ? E : 2 * E;
    unsigned d = (unsigned)v[dbase + s * i];
    if (d < (unsigned)N) atomicAdd(&g_cnt[d], 1);
}

// Single-block scan: 1024 threads, contiguous chunks + smem Hillis-Steele.
__global__ void k_scan(int N, int E)
{
    __shared__ int sums[1024];
    int t = threadIdx.x;
    int ch  = (N + 1023) >> 10;
    int beg = t * ch;
    int end = min(beg + ch, N);

    int s = 0;
    for (int i = beg; i < end; i++) s += g_cnt[i];
    sums[t] = s;
    __syncthreads();
    for (int o = 1; o < 1024; o <<= 1) {
        int v = (t >= o) ? sums[t - o] : 0;
        __syncthreads();
        sums[t] += v;
        __syncthreads();
    }
    int run = (t > 0) ? sums[t - 1] : 0;
    for (int i = beg; i < end; i++) {
        int c = g_cnt[i];
        g_off[i]    = run;
        g_cursor[i] = run;
        g_dinv[i]   = rsqrtf((float)(c + 1));         // +1 self loop
        run += c;
    }
    if (t == 0) g_off[N] = E;
}

__global__ void k_fill(const int* __restrict__ v, int E, int N)
{
    int i = blockIdx.x * blockDim.x + threadIdx.x;
    if (i >= E) return;
    int is32  = g_odd_or;
    int s     = is32 ? 1 : 2;
    int dbase = is32 ? E : 2 * E;
    unsigned d  = (unsigned)v[dbase + s * i];
    unsigned sr = (unsigned)v[s * i];
    if (d < (unsigned)N && sr < (unsigned)N) {
        int pos = atomicAdd(&g_cursor[d], 1);
        g_csr_src[pos] = (int)sr;
    }
}

// ---------------------------------------------------------------------------
// GEMM (f32x2): H[row] = (X[row] @ W) * dinv[row]
//   64-row tile, KC=32, 256 threads. x stored in smem as duplicated f32x2
//   pairs (pack once per tile). W stored as column-pair f32x2. Inner loop is
//   pure LDS + FFMA2: 2x fp32 FLOP per issue, bit-exact fp32 results.
// ---------------------------------------------------------------------------
template <int DOUT, int LAYER>
__global__ void k_gemm(const float* __restrict__ Xp,
                       const float* __restrict__ W, int N)
{
    constexpr int TR  = 64;
    constexpr int KC  = 32;
    constexpr int CG  = DOUT / 4;          // 32 (dh=128) or 16 (dout=64)
    constexpr int RG  = 256 / CG;          // 8 or 16
    constexpr int RPT = TR / RG;           // 8 or 4

    const float* X = (LAYER == 0) ? Xp : g_x2;
    float*       H = (LAYER == 0) ? g_hs : g_hs2;

    __shared__ unsigned long long xs2[TR * KC];          // x duplicated pairs
    __shared__ unsigned long long ws2[KC * (DOUT / 2)];  // w column pairs

    int t    = threadIdx.x;
    int cg   = t % CG;
    int rg   = t / CG;
    int row0 = blockIdx.x * TR;

    unsigned long long acc0[RPT], acc1[RPT];
#pragma unroll
    for (int r = 0; r < RPT; r++) { acc0[r] = 0ull; acc1[r] = 0ull; }

    for (int kk = 0; kk < 128; kk += KC) {
        // x tile: TR x KC, duplicated-pair packed
        for (int idx = t; idx < TR * (KC / 4); idx += 256) {
            int r  = idx / (KC / 4);
            int c4 = idx % (KC / 4);
            int row = row0 + r;
            float4 v = make_float4(0.f, 0.f, 0.f, 0.f);
            if (row < N)
                v = *(const float4*)&X[row * 128 + kk + c4 * 4];
            xs2[r * KC + c4 * 4 + 0] = pack2(v.x, v.x);
            xs2[r * KC + c4 * 4 + 1] = pack2(v.y, v.y);
            xs2[r * KC + c4 * 4 + 2] = pack2(v.z, v.z);
            xs2[r * KC + c4 * 4 + 3] = pack2(v.w, v.w);
        }
        // w tile: KC x DOUT, column-pair packed
        for (int idx = t; idx < KC * (DOUT / 4); idx += 256) {
            int k  = idx / (DOUT / 4);
            int c4 = idx % (DOUT / 4);
            float4 w = *(const float4*)&W[(kk + k) * DOUT + c4 * 4];
            ws2[k * (DOUT / 2) + c4 * 2 + 0] = pack2(w.x, w.y);
            ws2[k * (DOUT / 2) + c4 * 2 + 1] = pack2(w.z, w.w);
        }
        __syncthreads();

#pragma unroll
        for (int k = 0; k < KC; k++) {
            // 16B contiguous -> single LDS.128
            ulonglong2 w = *(const ulonglong2*)&ws2[k * (DOUT / 2) + cg * 2];
#pragma unroll
            for (int r = 0; r < RPT; r++) {
                unsigned long long xd = xs2[(rg * RPT + r) * KC + k];
                ffma2(acc0[r], xd, w.x);
                ffma2(acc1[r], xd, w.y);
            }
        }
        __syncthreads();
    }

#pragma unroll
    for (int r = 0; r < RPT; r++) {
        int row = row0 + rg * RPT + r;
        if (row < N) {
            float s = g_dinv[row];
            float x0, x1, x2, x3;
            unpack2(acc0[r], x0, x1);
            unpack2(acc1[r], x2, x3);
            float4 o;
            o.x = x0 * s; o.y = x1 * s; o.z = x2 * s; o.w = x3 * s;
            *(float4*)&H[row * DOUT + cg * 4] = o;
        }
    }
}

// ---------------------------------------------------------------------------
// Aggregate per dst node: OUT[d] = dinv[d]*(HS[d] + sum_in HS[src]) + b (+relu)
//   4-way unrolled with independent accumulators -> MLP=4 toward L2.
// ---------------------------------------------------------------------------
template <int DOUT, bool RELU, int LAYER>
__global__ void k_agg(const float* __restrict__ bias,
                      float* __restrict__ outp, int N)
{
    constexpr int TPN = DOUT / 4;         // threads per node (float4 lanes)
    constexpr int NPB = 256 / TPN;        // nodes per block

    const float* HS  = (LAYER == 0) ? g_hs : g_hs2;
    float*       OUT = (LAYER == 0) ? g_x2 : outp;

    int t    = threadIdx.x;
    int node = blockIdx.x * NPB + t / TPN;
    int c    = (t % TPN) * 4;
    if (node >= N) return;

    float4 a0 = *(const float4*)&HS[node * DOUT + c];   // self loop
    float4 a1 = make_float4(0.f, 0.f, 0.f, 0.f);
    float4 a2 = make_float4(0.f, 0.f, 0.f, 0.f);
    float4 a3 = make_float4(0.f, 0.f, 0.f, 0.f);

    int i = g_off[node];
    int e = g_off[node + 1];
    for (; i + 4 <= e; i += 4) {
        int s0 = g_csr_src[i + 0];
        int s1 = g_csr_src[i + 1];
        int s2 = g_csr_src[i + 2];
        int s3 = g_csr_src[i + 3];
        float4 v0 = *(const float4*)&HS[s0 * DOUT + c];
        float4 v1 = *(const float4*)&HS[s1 * DOUT + c];
        float4 v2 = *(const float4*)&HS[s2 * DOUT + c];
        float4 v3 = *(const float4*)&HS[s3 * DOUT + c];
        a0.x += v0.x; a0.y += v0.y; a0.z += v0.z; a0.w += v0.w;
        a1.x += v1.x; a1.y += v1.y; a1.z += v1.z; a1.w += v1.w;
        a2.x += v2.x; a2.y += v2.y; a2.z += v2.z; a2.w += v2.w;
        a3.x += v3.x; a3.y += v3.y; a3.z += v3.z; a3.w += v3.w;
    }
    for (; i < e; i++) {
        int s0 = g_csr_src[i];
        float4 v = *(const float4*)&HS[s0 * DOUT + c];
        a0.x += v.x; a0.y += v.y; a0.z += v.z; a0.w += v.w;
    }
    a0.x += a1.x + a2.x + a3.x;
    a0.y += a1.y + a2.y + a3.y;
    a0.z += a1.z + a2.z + a3.z;
    a0.w += a1.w + a2.w + a3.w;

    float d  = g_dinv[node];
    float4 b = *(const float4*)&bias[c];
    float4 o;
    o.x = a0.x * d + b.x;
    o.y = a0.y * d + b.y;
    o.z = a0.z * d + b.z;
    o.w = a0.w * d + b.w;
    if (RELU) {
        o.x = fmaxf(o.x, 0.f);
        o.y = fmaxf(o.y, 0.f);
        o.z = fmaxf(o.z, 0.f);
        o.w = fmaxf(o.w, 0.f);
    }
    *(float4*)&OUT[node * DOUT + c] = o;
}

// ---------------------------------------------------------------------------
extern "C" void kernel_launch(void* const* d_in, const int* in_sizes, int n_in,
                              void* d_out, int out_size)
{
    const float* e_prev = (const float*)d_in[0];
    const int*   ei     = (const int*)d_in[1];   // int32 view; dtype detected
    const float* W1     = (const float*)d_in[2];
    const float* b1     = (const float*)d_in[3];
    const float* W2     = (const float*)d_in[4];
    const float* b2     = (const float*)d_in[5];
    float*       out    = (float*)d_out;

    int N = in_sizes[0] / 128;   // 50000
    int E = in_sizes[1] / 2;     // 800000 (element count, dtype-independent)

    // CSR build
    k_init<<<(N + 255) / 256, 256>>>(ei, N);
    k_hist<<<(E + 255) / 256, 256>>>(ei, E, N);
    k_scan<<<1, 1024>>>(N, E);
    k_fill<<<(E + 255) / 256, 256>>>(ei, E, N);

    // Layer 1
    k_gemm<128, 0><<<(N + 63) / 64, 256>>>(e_prev, W1, N);
    {
        constexpr int NPB = 256 / (128 / 4);      // 8 nodes per block
        k_agg<128, true, 0><<<(N + NPB - 1) / NPB, 256>>>(b1, nullptr, N);
    }

    // Layer 2
    k_gemm<64, 1><<<(N + 63) / 64, 256>>>(nullptr, W2, N);
    {
        constexpr int NPB = 256 / (64 / 4);       // 16 nodes per block
        k_agg<64, false, 1><<<(N + NPB - 1) / NPB, 256>>>(b2, out, N);
    }
}

// round 6
// speedup vs baseline: 1.1307x; 1.1307x over previous
#include <cuda_runtime.h>
#include <cuda_fp16.h>

// ---------------------------------------------------------------------------
// GNNEncoder: 2-layer GCN. out[d] = dinv[d]*sum_{(s,d)}(x[s]@W)*dinv[s] + b
// R6: R5 design with the k_agg epilogue UB fixed (float a[8] -> explicit
//     float4s; no cross-variable pointer indexing).
//   - register-tiled FFMA2 GEMM (K-parity pairing, smem broadcast + swizzle)
//   - fp16 storage for gathered tensors (halved L2 traffic, fp32 accumulate)
//   - 4-edge-vectorized CSR build
// edge_index dtype detected at runtime (int32 vs int64-as-int32-pairs).
// All scratch in __device__ globals; graph-capturable (kernel launches only).
// ---------------------------------------------------------------------------

#define NODES_MAX 50000
#define EDGES_MAX 800000

__device__ int    g_odd_or;                 // !=0 => edge_index is int32
__device__ int    g_cnt[NODES_MAX];
__device__ int    g_off[NODES_MAX + 1];
__device__ int    g_cursor[NODES_MAX];
__device__ int    g_csr_src[EDGES_MAX];
__device__ float  g_dinv[NODES_MAX];
__device__ __half g_hs [NODES_MAX * 128];   // layer1 (x@W1)*dinv   (gathered)
__device__ float  g_x2 [NODES_MAX * 128];   // layer1 output (post relu)
__device__ __half g_hs2[NODES_MAX * 64];    // layer2 (x2@W2)*dinv  (gathered)

// ---- f32x2 helpers --------------------------------------------------------
__device__ __forceinline__ unsigned long long pack2(float lo, float hi)
{
    unsigned long long r;
    asm("mov.b64 %0, {%1, %2};" : "=l"(r) : "f"(lo), "f"(hi));
    return r;
}
__device__ __forceinline__ void unpack2(unsigned long long v, float& lo, float& hi)
{
    asm("mov.b64 {%0, %1}, %2;" : "=f"(lo), "=f"(hi) : "l"(v));
}
__device__ __forceinline__ void ffma2(unsigned long long& d,
                                      unsigned long long a,
                                      unsigned long long b)
{
    asm("fma.rn.f32x2 %0, %1, %2, %3;" : "=l"(d) : "l"(a), "l"(b), "l"(d));
}

// smem anti-conflict swizzle: insert a 2-entry (16B) gap every 16 entries.
__device__ __forceinline__ int swz(int i) { return i + ((i >> 4) << 1); }

// ---- CSR build --------------------------------------------------------------
__global__ void k_init(const int* __restrict__ v, int N)
{
    int i = blockIdx.x * blockDim.x + threadIdx.x;
    if (i < N) g_cnt[i] = 0;
    if (i == 0) g_odd_or = 0;
    // dtype detect: int64 viewed as int32 pairs -> odd words all zero.
    if (i < 256 && v[2 * i + 1] != 0) atomicOr(&g_odd_or, 1);
}

__global__ void k_hist(const int* __restrict__ v, int E, int N)
{
    int base = (blockIdx.x * blockDim.x + threadIdx.x) * 4;
    if (base >= E) return;
    int is32 = g_odd_or;
    if (base + 4 <= E) {
        unsigned d0, d1, d2, d3;
        if (is32) {
            int4 a = *(const int4*)&v[E + base];
            d0 = a.x; d1 = a.y; d2 = a.z; d3 = a.w;
        } else {
            int4 a = *(const int4*)&v[2 * E + 2 * base];
            int4 b = *(const int4*)&v[2 * E + 2 * base + 4];
            d0 = a.x; d1 = a.z; d2 = b.x; d3 = b.z;
        }
        if (d0 < (unsigned)N) atomicAdd(&g_cnt[d0], 1);
        if (d1 < (unsigned)N) atomicAdd(&g_cnt[d1], 1);
        if (d2 < (unsigned)N) atomicAdd(&g_cnt[d2], 1);
        if (d3 < (unsigned)N) atomicAdd(&g_cnt[d3], 1);
    } else {
        int s = is32 ? 1 : 2, dbase = is32 ? E : 2 * E;
        for (int i = base; i < E; i++) {
            unsigned d = (unsigned)v[dbase + s * i];
            if (d < (unsigned)N) atomicAdd(&g_cnt[d], 1);
        }
    }
}

// Single-block scan: 1024 threads, contiguous chunks + smem Hillis-Steele.
__global__ void k_scan(int N, int E)
{
    __shared__ int sums[1024];
    int t = threadIdx.x;
    int ch  = (N + 1023) >> 10;
    int beg = t * ch;
    int end = min(beg + ch, N);

    int s = 0;
    for (int i = beg; i < end; i++) s += g_cnt[i];
    sums[t] = s;
    __syncthreads();
    for (int o = 1; o < 1024; o <<= 1) {
        int vv = (t >= o) ? sums[t - o] : 0;
        __syncthreads();
        sums[t] += vv;
        __syncthreads();
    }
    int run = (t > 0) ? sums[t - 1] : 0;
    for (int i = beg; i < end; i++) {
        int c = g_cnt[i];
        g_off[i]    = run;
        g_cursor[i] = run;
        g_dinv[i]   = rsqrtf((float)(c + 1));         // +1 self loop
        run += c;
    }
    if (t == 0) g_off[N] = E;
}

__global__ void k_fill(const int* __restrict__ v, int E, int N)
{
    int base = (blockIdx.x * blockDim.x + threadIdx.x) * 4;
    if (base >= E) return;
    int is32 = g_odd_or;
    if (base + 4 <= E) {
        unsigned s0, s1, s2, s3, d0, d1, d2, d3;
        if (is32) {
            int4 a = *(const int4*)&v[base];
            int4 b = *(const int4*)&v[E + base];
            s0 = a.x; s1 = a.y; s2 = a.z; s3 = a.w;
            d0 = b.x; d1 = b.y; d2 = b.z; d3 = b.w;
        } else {
            int4 a = *(const int4*)&v[2 * base];
            int4 b = *(const int4*)&v[2 * base + 4];
            int4 c = *(const int4*)&v[2 * E + 2 * base];
            int4 d = *(const int4*)&v[2 * E + 2 * base + 4];
            s0 = a.x; s1 = a.z; s2 = b.x; s3 = b.z;
            d0 = c.x; d1 = c.z; d2 = d.x; d3 = d.z;
        }
        if (d0 < (unsigned)N && s0 < (unsigned)N)
            g_csr_src[atomicAdd(&g_cursor[d0], 1)] = (int)s0;
        if (d1 < (unsigned)N && s1 < (unsigned)N)
            g_csr_src[atomicAdd(&g_cursor[d1], 1)] = (int)s1;
        if (d2 < (unsigned)N && s2 < (unsigned)N)
            g_csr_src[atomicAdd(&g_cursor[d2], 1)] = (int)s2;
        if (d3 < (unsigned)N && s3 < (unsigned)N)
            g_csr_src[atomicAdd(&g_cursor[d3], 1)] = (int)s3;
    } else {
        int s = is32 ? 1 : 2, dbase = is32 ? E : 2 * E;
        for (int i = base; i < E; i++) {
            unsigned d  = (unsigned)v[dbase + s * i];
            unsigned sr = (unsigned)v[s * i];
            if (d < (unsigned)N && sr < (unsigned)N)
                g_csr_src[atomicAdd(&g_cursor[d], 1)] = (int)sr;
        }
    }
}

// ---------------------------------------------------------------------------
// GEMM (FFMA2, K-parity pairing): H16[row] = fp16((X[row] @ W) * dinv[row])
//   Block 256 thr = 8 warps. Warp tile 32x32, thread tile 8 rows x 4 cols.
//   acc[r][c] is an f32x2 pair: lanes = (even-k, odd-k) partial sums.
// ---------------------------------------------------------------------------
template <int DOUT, int LAYER>
__global__ void __launch_bounds__(256)
k_gemm(const float* __restrict__ Xp, const float* __restrict__ W, int N)
{
    constexpr int KC  = 32;            // K chunk
    constexpr int NK2 = KC / 2;        // 16 k-pairs per chunk
    constexpr int WC  = DOUT / 32;     // warp-cols (4 or 2)
    constexpr int WR  = 8 / WC;        // warp-rows (2 or 4)
    constexpr int BM  = WR * 32;       // block rows (64 or 128)
    constexpr int SX  = BM + (BM >> 4) * 2 + 2;    // swizzled slab strides
    constexpr int SW  = DOUT + (DOUT >> 4) * 2 + 2;

    const float* X = (LAYER == 0) ? Xp : g_x2;
    __half*      H = (LAYER == 0) ? g_hs : g_hs2;

    __shared__ unsigned long long xs2[NK2 * SX];
    __shared__ unsigned long long ws2[NK2 * SW];

    int t    = threadIdx.x;
    int w    = t >> 5;
    int lane = t & 31;
    int rg   = lane >> 3;              // 0..3
    int cg   = lane & 7;               // 0..7
    int warpRow = w / WC;
    int warpCol = w % WC;
    int rowL0   = warpRow * 32 + rg * 8;           // local row base (8 rows)
    int colBase = warpCol * 32 + cg * 4;           // local col base (4 cols)
    int row0    = blockIdx.x * BM;

    unsigned long long acc[8][4];
#pragma unroll
    for (int i = 0; i < 8; i++)
#pragma unroll
        for (int j = 0; j < 4; j++) acc[i][j] = 0ull;

    for (int kk = 0; kk < 128; kk += KC) {
        // ---- stage X chunk: xs2[k2][swz(rowLocal)] = (x_eventk, x_oddk)
#pragma unroll
        for (int u = 0; u < BM / 32; u++) {
            int idx = u * 256 + t;                  // BM*8 units
            int r   = idx >> 3;
            int j4  = idx & 7;                      // float4 index in chunk
            int row = row0 + r;
            float4 x = make_float4(0.f, 0.f, 0.f, 0.f);
            if (row < N) x = *(const float4*)&X[row * 128 + kk + j4 * 4];
            xs2[(2 * j4)     * SX + swz(r)] = pack2(x.x, x.y);
            xs2[(2 * j4 + 1) * SX + swz(r)] = pack2(x.z, x.w);
        }
        // ---- stage W chunk: ws2[k2][swz(col)] = (W[2k2][c], W[2k2+1][c])
#pragma unroll
        for (int u = 0; u < DOUT / 64; u++) {
            int idx = u * 256 + t;                  // 4*DOUT units
            int k2  = idx / (DOUT / 4);
            int c4  = idx % (DOUT / 4);
            const float* wp = &W[(kk + 2 * k2) * DOUT + c4 * 4];
            float4 a = *(const float4*)wp;
            float4 b = *(const float4*)(wp + DOUT);
            int p = k2 * SW + swz(c4 * 4);
            ulonglong2 p0; p0.x = pack2(a.x, b.x); p0.y = pack2(a.y, b.y);
            ulonglong2 p1; p1.x = pack2(a.z, b.z); p1.y = pack2(a.w, b.w);
            *(ulonglong2*)&ws2[p]     = p0;
            *(ulonglong2*)&ws2[p + 2] = p1;
        }
        __syncthreads();

#pragma unroll
        for (int k2 = 0; k2 < NK2; k2++) {
            ulonglong2 xv[4];
#pragma unroll
            for (int j = 0; j < 4; j++)
                xv[j] = *(const ulonglong2*)&xs2[k2 * SX + swz(rowL0 + 2 * j)];
            ulonglong2 wv0 = *(const ulonglong2*)&ws2[k2 * SW + swz(colBase)];
            ulonglong2 wv1 = *(const ulonglong2*)&ws2[k2 * SW + swz(colBase + 2)];
#pragma unroll
            for (int j = 0; j < 4; j++) {
                ffma2(acc[2 * j][0],     xv[j].x, wv0.x);
                ffma2(acc[2 * j][1],     xv[j].x, wv0.y);
                ffma2(acc[2 * j][2],     xv[j].x, wv1.x);
                ffma2(acc[2 * j][3],     xv[j].x, wv1.y);
                ffma2(acc[2 * j + 1][0], xv[j].y, wv0.x);
                ffma2(acc[2 * j + 1][1], xv[j].y, wv0.y);
                ffma2(acc[2 * j + 1][2], xv[j].y, wv1.x);
                ffma2(acc[2 * j + 1][3], xv[j].y, wv1.y);
            }
        }
        __syncthreads();
    }

    // epilogue: fold k-parity pairs, scale by dinv, convert fp16, store
#pragma unroll
    for (int i = 0; i < 8; i++) {
        int row = row0 + rowL0 + i;
        if (row < N) {
            float s = g_dinv[row];
            float f[4];
#pragma unroll
            for (int j = 0; j < 4; j++) {
                float lo, hi;
                unpack2(acc[i][j], lo, hi);
                f[j] = (lo + hi) * s;
            }
            __half2 h01 = __floats2half2_rn(f[0], f[1]);
            __half2 h23 = __floats2half2_rn(f[2], f[3]);
            uint2 o;
            o.x = *(unsigned*)&h01;
            o.y = *(unsigned*)&h23;
            *(uint2*)&H[row * DOUT + colBase] = o;
        }
    }
}

// ---------------------------------------------------------------------------
// Aggregate per dst node: OUT[d] = dinv[d]*(HS[d] + sum_in HS[src]) + b (+relu)
//   HS is fp16 (halved gather traffic); accumulation fp32; 4-way edge unroll.
//   Each thread owns 8 columns (one uint4 = 8 halves per row).
// ---------------------------------------------------------------------------
template <int DOUT, bool RELU, int LAYER>
__global__ void k_agg(const float* __restrict__ bias,
                      float* __restrict__ outp, int N)
{
    constexpr int TPN = DOUT / 8;         // threads per node
    constexpr int NPB = 256 / TPN;        // nodes per block

    const __half* HS  = (LAYER == 0) ? g_hs : g_hs2;
    float*        OUT = (LAYER == 0) ? g_x2 : outp;

    int t    = threadIdx.x;
    int node = blockIdx.x * NPB + t / TPN;
    int c8   = (t % TPN) * 8;
    if (node >= N) return;

    float a[8];
    {   // self loop
        uint4 v = *(const uint4*)&HS[node * DOUT + c8];
        float2 f0 = __half22float2(*(__half2*)&v.x);
        float2 f1 = __half22float2(*(__half2*)&v.y);
        float2 f2 = __half22float2(*(__half2*)&v.z);
        float2 f3 = __half22float2(*(__half2*)&v.w);
        a[0] = f0.x; a[1] = f0.y; a[2] = f1.x; a[3] = f1.y;
        a[4] = f2.x; a[5] = f2.y; a[6] = f3.x; a[7] = f3.y;
    }

    int i = g_off[node];
    int e = g_off[node + 1];
    for (; i + 4 <= e; i += 4) {
        int s0 = g_csr_src[i + 0];
        int s1 = g_csr_src[i + 1];
        int s2 = g_csr_src[i + 2];
        int s3 = g_csr_src[i + 3];
        uint4 v0 = *(const uint4*)&HS[s0 * DOUT + c8];
        uint4 v1 = *(const uint4*)&HS[s1 * DOUT + c8];
        uint4 v2 = *(const uint4*)&HS[s2 * DOUT + c8];
        uint4 v3 = *(const uint4*)&HS[s3 * DOUT + c8];
#pragma unroll
        for (int q = 0; q < 4; q++) {
            unsigned w0 = (&v0.x)[q], w1 = (&v1.x)[q],
                     w2 = (&v2.x)[q], w3 = (&v3.x)[q];
            float2 f0 = __half22float2(*(__half2*)&w0);
            float2 f1 = __half22float2(*(__half2*)&w1);
            float2 f2 = __half22float2(*(__half2*)&w2);
            float2 f3 = __half22float2(*(__half2*)&w3);
            a[2 * q]     += f0.x + f1.x + f2.x + f3.x;
            a[2 * q + 1] += f0.y + f1.y + f2.y + f3.y;
        }
    }
    for (; i < e; i++) {
        int s0 = g_csr_src[i];
        uint4 v = *(const uint4*)&HS[s0 * DOUT + c8];
#pragma unroll
        for (int q = 0; q < 4; q++) {
            unsigned w0 = (&v.x)[q];
            float2 f = __half22float2(*(__half2*)&w0);
            a[2 * q]     += f.x;
            a[2 * q + 1] += f.y;
        }
    }

    float d = g_dinv[node];
    float r[8];
#pragma unroll
    for (int q = 0; q < 8; q++) {
        float o = a[q] * d + bias[c8 + q];
        if (RELU) o = fmaxf(o, 0.f);
        r[q] = o;
    }
    float4 ob0 = make_float4(r[0], r[1], r[2], r[3]);
    float4 ob1 = make_float4(r[4], r[5], r[6], r[7]);
    *(float4*)&OUT[node * DOUT + c8]     = ob0;
    *(float4*)&OUT[node * DOUT + c8 + 4] = ob1;
}

// ---------------------------------------------------------------------------
extern "C" void kernel_launch(void* const* d_in, const int* in_sizes, int n_in,
                              void* d_out, int out_size)
{
    const float* e_prev = (const float*)d_in[0];
    const int*   ei     = (const int*)d_in[1];   // int32 view; dtype detected
    const float* W1     = (const float*)d_in[2];
    const float* b1     = (const float*)d_in[3];
    const float* W2     = (const float*)d_in[4];
    const float* b2     = (const float*)d_in[5];
    float*       out    = (float*)d_out;

    int N = in_sizes[0] / 128;   // 50000
    int E = in_sizes[1] / 2;     // 800000 (element count, dtype-independent)

    // CSR build
    k_init<<<(N + 255) / 256, 256>>>(ei, N);
    k_hist<<<(E / 4 + 255) / 256, 256>>>(ei, E, N);
    k_scan<<<1, 1024>>>(N, E);
    k_fill<<<(E / 4 + 255) / 256, 256>>>(ei, E, N);

    // Layer 1: BM=64
    k_gemm<128, 0><<<(N + 63) / 64, 256>>>(e_prev, W1, N);
    {
        constexpr int NPB = 256 / (128 / 8);      // 16 nodes per block
        k_agg<128, true, 0><<<(N + NPB - 1) / NPB, 256>>>(b1, nullptr, N);
    }

    // Layer 2: BM=128
    k_gemm<64, 1><<<(N + 127) / 128, 256>>>(nullptr, W2, N);
    {
        constexpr int NPB = 256 / (64 / 8);       // 32 nodes per block
        k_agg<64, false, 1><<<(N + NPB - 1) / NPB, 256>>>(b2, out, N);
    }
}

// round 7
// speedup vs baseline: 1.1549x; 1.0214x over previous
#include <cuda_runtime.h>
#include <cuda_fp16.h>

// ---------------------------------------------------------------------------
// GNNEncoder: 2-layer GCN. out[d] = dinv[d]*sum_{(s,d)}(x[s]@W)*dinv[s] + b
// R7: CSR build (init->hist->scan->fill) overlapped with GEMM-1 via forked
//     graph-capture branch (side stream + events, created in static init).
//     dinv[src] folding moved from GEMM epilogue into aggregation (per-edge
//     FMA), removing gemm1's dependency on the scan.
//   - register-tiled FFMA2 GEMM (K-parity pairing, smem broadcast + swizzle)
//   - fp16 storage for gathered tensors (fp32 accumulation)
// All scratch in __device__ globals; graph-capturable (kernels + events only).
// ---------------------------------------------------------------------------

#define NODES_MAX 50000
#define EDGES_MAX 800000

__device__ int    g_odd_or;                 // !=0 => edge_index is int32
__device__ int    g_cnt[NODES_MAX];
__device__ int    g_off[NODES_MAX + 1];
__device__ int    g_cursor[NODES_MAX];
__device__ int    g_csr_src[EDGES_MAX];
__device__ float  g_dinv[NODES_MAX];
__device__ __half g_hs [NODES_MAX * 128];   // layer1 x@W1          (gathered)
__device__ float  g_x2 [NODES_MAX * 128];   // layer1 output (post relu)
__device__ __half g_hs2[NODES_MAX * 64];    // layer2 x2@W2         (gathered)

// ---- side stream for forked capture branch (created once, before harness
// checkpoints; deterministic work every call; fallback = sequential) --------
namespace {
struct SideStream {
    cudaStream_t s2 = nullptr;
    cudaEvent_t  fork = nullptr, joinB = nullptr;
    bool ok = false;
    SideStream()
    {
        ok = (cudaStreamCreateWithFlags(&s2, cudaStreamNonBlocking) == cudaSuccess) &&
             (cudaEventCreateWithFlags(&fork, cudaEventDisableTiming) == cudaSuccess) &&
             (cudaEventCreateWithFlags(&joinB, cudaEventDisableTiming) == cudaSuccess);
    }
};
SideStream g_ss;
}

// ---- f32x2 helpers --------------------------------------------------------
__device__ __forceinline__ unsigned long long pack2(float lo, float hi)
{
    unsigned long long r;
    asm("mov.b64 %0, {%1, %2};" : "=l"(r) : "f"(lo), "f"(hi));
    return r;
}
__device__ __forceinline__ void unpack2(unsigned long long v, float& lo, float& hi)
{
    asm("mov.b64 {%0, %1}, %2;" : "=f"(lo), "=f"(hi) : "l"(v));
}
__device__ __forceinline__ void ffma2(unsigned long long& d,
                                      unsigned long long a,
                                      unsigned long long b)
{
    asm("fma.rn.f32x2 %0, %1, %2, %3;" : "=l"(d) : "l"(a), "l"(b), "l"(d));
}

// smem anti-conflict swizzle: insert a 2-entry (16B) gap every 16 entries.
__device__ __forceinline__ int swz(int i) { return i + ((i >> 4) << 1); }

// ---- CSR build --------------------------------------------------------------
__global__ void k_init(const int* __restrict__ v, int N)
{
    int i = blockIdx.x * blockDim.x + threadIdx.x;
    if (i < N) g_cnt[i] = 0;
    if (i == 0) g_odd_or = 0;
    // dtype detect: int64 viewed as int32 pairs -> odd words all zero.
    if (i < 256 && v[2 * i + 1] != 0) atomicOr(&g_odd_or, 1);
}

__global__ void k_hist(const int* __restrict__ v, int E, int N)
{
    int base = (blockIdx.x * blockDim.x + threadIdx.x) * 4;
    if (base >= E) return;
    int is32 = g_odd_or;
    if (base + 4 <= E) {
        unsigned d0, d1, d2, d3;
        if (is32) {
            int4 a = *(const int4*)&v[E + base];
            d0 = a.x; d1 = a.y; d2 = a.z; d3 = a.w;
        } else {
            int4 a = *(const int4*)&v[2 * E + 2 * base];
            int4 b = *(const int4*)&v[2 * E + 2 * base + 4];
            d0 = a.x; d1 = a.z; d2 = b.x; d3 = b.z;
        }
        if (d0 < (unsigned)N) atomicAdd(&g_cnt[d0], 1);
        if (d1 < (unsigned)N) atomicAdd(&g_cnt[d1], 1);
        if (d2 < (unsigned)N) atomicAdd(&g_cnt[d2], 1);
        if (d3 < (unsigned)N) atomicAdd(&g_cnt[d3], 1);
    } else {
        int s = is32 ? 1 : 2, dbase = is32 ? E : 2 * E;
        for (int i = base; i < E; i++) {
            unsigned d = (unsigned)v[dbase + s * i];
            if (d < (unsigned)N) atomicAdd(&g_cnt[d], 1);
        }
    }
}

// Single-block scan: 1024 threads, contiguous chunks + smem Hillis-Steele.
__global__ void k_scan(int N, int E)
{
    __shared__ int sums[1024];
    int t = threadIdx.x;
    int ch  = (N + 1023) >> 10;
    int beg = t * ch;
    int end = min(beg + ch, N);

    int s = 0;
    for (int i = beg; i < end; i++) s += g_cnt[i];
    sums[t] = s;
    __syncthreads();
    for (int o = 1; o < 1024; o <<= 1) {
        int vv = (t >= o) ? sums[t - o] : 0;
        __syncthreads();
        sums[t] += vv;
        __syncthreads();
    }
    int run = (t > 0) ? sums[t - 1] : 0;
    for (int i = beg; i < end; i++) {
        int c = g_cnt[i];
        g_off[i]    = run;
        g_cursor[i] = run;
        g_dinv[i]   = rsqrtf((float)(c + 1));         // +1 self loop
        run += c;
    }
    if (t == 0) g_off[N] = E;
}

__global__ void k_fill(const int* __restrict__ v, int E, int N)
{
    int base = (blockIdx.x * blockDim.x + threadIdx.x) * 4;
    if (base >= E) return;
    int is32 = g_odd_or;
    if (base + 4 <= E) {
        unsigned s0, s1, s2, s3, d0, d1, d2, d3;
        if (is32) {
            int4 a = *(const int4*)&v[base];
            int4 b = *(const int4*)&v[E + base];
            s0 = a.x; s1 = a.y; s2 = a.z; s3 = a.w;
            d0 = b.x; d1 = b.y; d2 = b.z; d3 = b.w;
        } else {
            int4 a = *(const int4*)&v[2 * base];
            int4 b = *(const int4*)&v[2 * base + 4];
            int4 c = *(const int4*)&v[2 * E + 2 * base];
            int4 d = *(const int4*)&v[2 * E + 2 * base + 4];
            s0 = a.x; s1 = a.z; s2 = b.x; s3 = b.z;
            d0 = c.x; d1 = c.z; d2 = d.x; d3 = d.z;
        }
        if (d0 < (unsigned)N && s0 < (unsigned)N)
            g_csr_src[atomicAdd(&g_cursor[d0], 1)] = (int)s0;
        if (d1 < (unsigned)N && s1 < (unsigned)N)
            g_csr_src[atomicAdd(&g_cursor[d1], 1)] = (int)s1;
        if (d2 < (unsigned)N && s2 < (unsigned)N)
            g_csr_src[atomicAdd(&g_cursor[d2], 1)] = (int)s2;
        if (d3 < (unsigned)N && s3 < (unsigned)N)
            g_csr_src[atomicAdd(&g_cursor[d3], 1)] = (int)s3;
    } else {
        int s = is32 ? 1 : 2, dbase = is32 ? E : 2 * E;
        for (int i = base; i < E; i++) {
            unsigned d  = (unsigned)v[dbase + s * i];
            unsigned sr = (unsigned)v[s * i];
            if (d < (unsigned)N && sr < (unsigned)N)
                g_csr_src[atomicAdd(&g_cursor[d], 1)] = (int)sr;
        }
    }
}

// ---------------------------------------------------------------------------
// GEMM (FFMA2, K-parity pairing): H16[row] = fp16(X[row] @ W)   (NO dinv)
//   Block 256 thr = 8 warps. Warp tile 32x32, thread tile 8 rows x 4 cols.
// ---------------------------------------------------------------------------
template <int DOUT, int LAYER>
__global__ void __launch_bounds__(256)
k_gemm(const float* __restrict__ Xp, const float* __restrict__ W, int N)
{
    constexpr int KC  = 32;            // K chunk
    constexpr int NK2 = KC / 2;        // 16 k-pairs per chunk
    constexpr int WC  = DOUT / 32;     // warp-cols (4 or 2)
    constexpr int WR  = 8 / WC;        // warp-rows (2 or 4)
    constexpr int BM  = WR * 32;       // block rows (64 or 128)
    constexpr int SX  = BM + (BM >> 4) * 2 + 2;    // swizzled slab strides
    constexpr int SW  = DOUT + (DOUT >> 4) * 2 + 2;

    const float* X = (LAYER == 0) ? Xp : g_x2;
    __half*      H = (LAYER == 0) ? g_hs : g_hs2;

    __shared__ unsigned long long xs2[NK2 * SX];
    __shared__ unsigned long long ws2[NK2 * SW];

    int t    = threadIdx.x;
    int w    = t >> 5;
    int lane = t & 31;
    int rg   = lane >> 3;              // 0..3
    int cg   = lane & 7;               // 0..7
    int warpRow = w / WC;
    int warpCol = w % WC;
    int rowL0   = warpRow * 32 + rg * 8;           // local row base (8 rows)
    int colBase = warpCol * 32 + cg * 4;           // local col base (4 cols)
    int row0    = blockIdx.x * BM;

    unsigned long long acc[8][4];
#pragma unroll
    for (int i = 0; i < 8; i++)
#pragma unroll
        for (int j = 0; j < 4; j++) acc[i][j] = 0ull;

    for (int kk = 0; kk < 128; kk += KC) {
        // ---- stage X chunk: xs2[k2][swz(rowLocal)] = (x_eventk, x_oddk)
#pragma unroll
        for (int u = 0; u < BM / 32; u++) {
            int idx = u * 256 + t;                  // BM*8 units
            int r   = idx >> 3;
            int j4  = idx & 7;                      // float4 index in chunk
            int row = row0 + r;
            float4 x = make_float4(0.f, 0.f, 0.f, 0.f);
            if (row < N) x = *(const float4*)&X[row * 128 + kk + j4 * 4];
            xs2[(2 * j4)     * SX + swz(r)] = pack2(x.x, x.y);
            xs2[(2 * j4 + 1) * SX + swz(r)] = pack2(x.z, x.w);
        }
        // ---- stage W chunk: ws2[k2][swz(col)] = (W[2k2][c], W[2k2+1][c])
#pragma unroll
        for (int u = 0; u < DOUT / 64; u++) {
            int idx = u * 256 + t;                  // 4*DOUT units
            int k2  = idx / (DOUT / 4);
            int c4  = idx % (DOUT / 4);
            const float* wp = &W[(kk + 2 * k2) * DOUT + c4 * 4];
            float4 a = *(const float4*)wp;
            float4 b = *(const float4*)(wp + DOUT);
            int p = k2 * SW + swz(c4 * 4);
            ulonglong2 p0; p0.x = pack2(a.x, b.x); p0.y = pack2(a.y, b.y);
            ulonglong2 p1; p1.x = pack2(a.z, b.z); p1.y = pack2(a.w, b.w);
            *(ulonglong2*)&ws2[p]     = p0;
            *(ulonglong2*)&ws2[p + 2] = p1;
        }
        __syncthreads();

#pragma unroll
        for (int k2 = 0; k2 < NK2; k2++) {
            ulonglong2 xv[4];
#pragma unroll
            for (int j = 0; j < 4; j++)
                xv[j] = *(const ulonglong2*)&xs2[k2 * SX + swz(rowL0 + 2 * j)];
            ulonglong2 wv0 = *(const ulonglong2*)&ws2[k2 * SW + swz(colBase)];
            ulonglong2 wv1 = *(const ulonglong2*)&ws2[k2 * SW + swz(colBase + 2)];
#pragma unroll
            for (int j = 0; j < 4; j++) {
                ffma2(acc[2 * j][0],     xv[j].x, wv0.x);
                ffma2(acc[2 * j][1],     xv[j].x, wv0.y);
                ffma2(acc[2 * j][2],     xv[j].x, wv1.x);
                ffma2(acc[2 * j][3],     xv[j].x, wv1.y);
                ffma2(acc[2 * j + 1][0], xv[j].y, wv0.x);
                ffma2(acc[2 * j + 1][1], xv[j].y, wv0.y);
                ffma2(acc[2 * j + 1][2], xv[j].y, wv1.x);
                ffma2(acc[2 * j + 1][3], xv[j].y, wv1.y);
            }
        }
        __syncthreads();
    }

    // epilogue: fold k-parity pairs, convert fp16, store
#pragma unroll
    for (int i = 0; i < 8; i++) {
        int row = row0 + rowL0 + i;
        if (row < N) {
            float f[4];
#pragma unroll
            for (int j = 0; j < 4; j++) {
                float lo, hi;
                unpack2(acc[i][j], lo, hi);
                f[j] = lo + hi;
            }
            __half2 h01 = __floats2half2_rn(f[0], f[1]);
            __half2 h23 = __floats2half2_rn(f[2], f[3]);
            uint2 o;
            o.x = *(unsigned*)&h01;
            o.y = *(unsigned*)&h23;
            *(uint2*)&H[row * DOUT + colBase] = o;
        }
    }
}

// ---------------------------------------------------------------------------
// Aggregate per dst node:
//   OUT[d] = dinv[d]*( HS[d]*dinv[d] + sum_in HS[src]*dinv[src] ) + b (+relu)
//   HS is fp16 (halved gather traffic); accumulation fp32; 4-way edge unroll.
// ---------------------------------------------------------------------------
template <int DOUT, bool RELU, int LAYER>
__global__ void k_agg(const float* __restrict__ bias,
                      float* __restrict__ outp, int N)
{
    constexpr int TPN = DOUT / 8;         // threads per node
    constexpr int NPB = 256 / TPN;        // nodes per block

    const __half* HS  = (LAYER == 0) ? g_hs : g_hs2;
    float*        OUT = (LAYER == 0) ? g_x2 : outp;

    int t    = threadIdx.x;
    int node = blockIdx.x * NPB + t / TPN;
    int c8   = (t % TPN) * 8;
    if (node >= N) return;

    float dnode = g_dinv[node];
    float a[8];
    {   // self loop: HS[d]*dinv[d]
        uint4 v = *(const uint4*)&HS[node * DOUT + c8];
        float2 f0 = __half22float2(*(__half2*)&v.x);
        float2 f1 = __half22float2(*(__half2*)&v.y);
        float2 f2 = __half22float2(*(__half2*)&v.z);
        float2 f3 = __half22float2(*(__half2*)&v.w);
        a[0] = f0.x * dnode; a[1] = f0.y * dnode;
        a[2] = f1.x * dnode; a[3] = f1.y * dnode;
        a[4] = f2.x * dnode; a[5] = f2.y * dnode;
        a[6] = f3.x * dnode; a[7] = f3.y * dnode;
    }

    int i = g_off[node];
    int e = g_off[node + 1];
    for (; i + 4 <= e; i += 4) {
        int s0 = g_csr_src[i + 0];
        int s1 = g_csr_src[i + 1];
        int s2 = g_csr_src[i + 2];
        int s3 = g_csr_src[i + 3];
        uint4 v0 = *(const uint4*)&HS[s0 * DOUT + c8];
        uint4 v1 = *(const uint4*)&HS[s1 * DOUT + c8];
        uint4 v2 = *(const uint4*)&HS[s2 * DOUT + c8];
        uint4 v3 = *(const uint4*)&HS[s3 * DOUT + c8];
        float dv0 = g_dinv[s0];
        float dv1 = g_dinv[s1];
        float dv2 = g_dinv[s2];
        float dv3 = g_dinv[s3];
#pragma unroll
        for (int q = 0; q < 4; q++) {
            unsigned w0 = (&v0.x)[q], w1 = (&v1.x)[q],
                     w2 = (&v2.x)[q], w3 = (&v3.x)[q];
            float2 f0 = __half22float2(*(__half2*)&w0);
            float2 f1 = __half22float2(*(__half2*)&w1);
            float2 f2 = __half22float2(*(__half2*)&w2);
            float2 f3 = __half22float2(*(__half2*)&w3);
            a[2 * q]     = fmaf(f0.x, dv0, a[2 * q]);
            a[2 * q]     = fmaf(f1.x, dv1, a[2 * q]);
            a[2 * q]     = fmaf(f2.x, dv2, a[2 * q]);
            a[2 * q]     = fmaf(f3.x, dv3, a[2 * q]);
            a[2 * q + 1] = fmaf(f0.y, dv0, a[2 * q + 1]);
            a[2 * q + 1] = fmaf(f1.y, dv1, a[2 * q + 1]);
            a[2 * q + 1] = fmaf(f2.y, dv2, a[2 * q + 1]);
            a[2 * q + 1] = fmaf(f3.y, dv3, a[2 * q + 1]);
        }
    }
    for (; i < e; i++) {
        int s0 = g_csr_src[i];
        uint4 v = *(const uint4*)&HS[s0 * DOUT + c8];
        float dv = g_dinv[s0];
#pragma unroll
        for (int q = 0; q < 4; q++) {
            unsigned w0 = (&v.x)[q];
            float2 f = __half22float2(*(__half2*)&w0);
            a[2 * q]     = fmaf(f.x, dv, a[2 * q]);
            a[2 * q + 1] = fmaf(f.y, dv, a[2 * q + 1]);
        }
    }

    float r[8];
#pragma unroll
    for (int q = 0; q < 8; q++) {
        float o = a[q] * dnode + bias[c8 + q];
        if (RELU) o = fmaxf(o, 0.f);
        r[q] = o;
    }
    float4 ob0 = make_float4(r[0], r[1], r[2], r[3]);
    float4 ob1 = make_float4(r[4], r[5], r[6], r[7]);
    *(float4*)&OUT[node * DOUT + c8]     = ob0;
    *(float4*)&OUT[node * DOUT + c8 + 4] = ob1;
}

// ---------------------------------------------------------------------------
extern "C" void kernel_launch(void* const* d_in, const int* in_sizes, int n_in,
                              void* d_out, int out_size)
{
    const float* e_prev = (const float*)d_in[0];
    const int*   ei     = (const int*)d_in[1];   // int32 view; dtype detected
    const float* W1     = (const float*)d_in[2];
    const float* b1     = (const float*)d_in[3];
    const float* W2     = (const float*)d_in[4];
    const float* b2     = (const float*)d_in[5];
    float*       out    = (float*)d_out;

    int N = in_sizes[0] / 128;   // 50000
    int E = in_sizes[1] / 2;     // 800000 (element count, dtype-independent)

    cudaStream_t s0 = 0;
    bool forked = g_ss.ok;
    cudaStream_t sg = forked ? g_ss.s2 : s0;   // stream for gemm1 branch

    if (forked) {
        cudaEventRecord(g_ss.fork, s0);
        cudaStreamWaitEvent(sg, g_ss.fork, 0);
    }

    // Branch B: layer-1 GEMM (independent of CSR build)
    k_gemm<128, 0><<<(N + 63) / 64, 256, 0, sg>>>(e_prev, W1, N);
    if (forked) {
        cudaEventRecord(g_ss.joinB, sg);
    }

    // Branch A: CSR build
    k_init<<<(N + 255) / 256, 256, 0, s0>>>(ei, N);
    k_hist<<<(E / 4 + 255) / 256, 256, 0, s0>>>(ei, E, N);
    k_scan<<<1, 1024, 0, s0>>>(N, E);
    k_fill<<<(E / 4 + 255) / 256, 256, 0, s0>>>(ei, E, N);

    if (forked) {
        cudaStreamWaitEvent(s0, g_ss.joinB, 0);
    }

    // Join: aggregation + layer 2 (sequential on s0)
    {
        constexpr int NPB = 256 / (128 / 8);      // 16 nodes per block
        k_agg<128, true, 0><<<(N + NPB - 1) / NPB, 256, 0, s0>>>(b1, nullptr, N);
    }
    k_gemm<64, 1><<<(N + 127) / 128, 256, 0, s0>>>(nullptr, W2, N);
    {
        constexpr int NPB = 256 / (64 / 8);       // 32 nodes per block
        k_agg<64, false, 1><<<(N + NPB - 1) / NPB, 256, 0, s0>>>(b2, out, N);
    }
}